// round 6
// baseline (speedup 1.0000x reference)
#include <cuda_runtime.h>
#include <cuda_fp16.h>
#include <math.h>

#define N_NODES 100000
#define N_EDGES 1600000
#define H 64
#define SCAN_T 1024
#define SCAN_B ((N_NODES + SCAN_T - 1) / SCAN_T)   // 98

// Scratch (device globals — no allocation allowed)
__device__ int    g_degi[N_NODES];
__device__ float  g_dinv[N_NODES];
__device__ int    g_rowptr[N_NODES];       // exclusive-within-block partials
__device__ int    g_bsum[SCAN_B];
__device__ int    g_boff[SCAN_B];          // exclusive block offsets
__device__ int    g_cnt[N_NODES];
__device__ int    g_ticket;
__device__ int2   g_edge[N_EDGES];         // {src, norm-as-bits}
__device__ __half g_yh0[(size_t)N_NODES * H];  // y ping
__device__ __half g_yh1[(size_t)N_NODES * H];  // y pong

#define FMA2(acc, a, b) \
    asm("fma.rn.f32x2 %0, %1, %2, %0;" : "+l"(acc) : "l"(a), "l"(b))

__global__ void zero_kernel() {
    int i = blockIdx.x * blockDim.x + threadIdx.x;
    if (i < N_NODES) { g_degi[i] = 0; g_cnt[i] = 0; }
    if (i == 0) g_ticket = 0;
}

__global__ void hist_kernel(const int* __restrict__ ei) {
    int e = blockIdx.x * blockDim.x + threadIdx.x;
    if (e < N_EDGES) atomicAdd(&g_degi[ei[N_EDGES + e]], 1);
}

// Per-block scan of degrees (+ fused dinv). Last block to finish also scans
// the 98 block sums into g_boff (decoupled via ticket + threadfence).
__global__ void __launch_bounds__(SCAN_T) scanA_kernel() {
    __shared__ int s[SCAN_T];
    __shared__ int s2[128];
    __shared__ int isLast;
    int t = threadIdx.x;
    int i = blockIdx.x * SCAN_T + t;
    int v = (i < N_NODES) ? g_degi[i] : 0;
    if (i < N_NODES) g_dinv[i] = rsqrtf((float)(v + 1));
    s[t] = v;
    __syncthreads();
    for (int off = 1; off < SCAN_T; off <<= 1) {
        int tmp = 0;
        if (t >= off) tmp = s[t - off];
        __syncthreads();
        if (t >= off) s[t] += tmp;
        __syncthreads();
    }
    if (i < N_NODES) g_rowptr[i] = s[t] - v;  // exclusive within block
    if (t == SCAN_T - 1) g_bsum[blockIdx.x] = s[t];

    if (t == 0) {
        __threadfence();
        int prev = atomicAdd(&g_ticket, 1);
        isLast = (prev == gridDim.x - 1) ? 1 : 0;
    }
    __syncthreads();
    if (!isLast) return;
    __threadfence();  // acquire bsum writes

    int v2 = (t < SCAN_B) ? g_bsum[t] : 0;
    if (t < 128) s2[t] = v2;
    __syncthreads();
    for (int off = 1; off < 128; off <<= 1) {
        int tmp = 0;
        if (t >= off && t < 128) tmp = s2[t - off];
        __syncthreads();
        if (t >= off && t < 128) s2[t] += tmp;
        __syncthreads();
    }
    if (t < SCAN_B) g_boff[t] = s2[t] - v2;  // exclusive
}

// CSR fill; applies g_boff on the fly.
__global__ void fill_kernel(const int* __restrict__ ei) {
    int e = blockIdx.x * blockDim.x + threadIdx.x;
    if (e >= N_EDGES) return;
    int s = ei[e];
    int d = ei[N_EDGES + e];
    int p = g_rowptr[d] + g_boff[d >> 10] + atomicAdd(&g_cnt[d], 1);
    int2 m;
    m.x = s;
    m.y = __float_as_int(g_dinv[s] * g_dinv[d]);
    g_edge[p] = m;
}

// Layer-1 GEMM only: y0 = emb @ W1, stored fp16.
__global__ void __launch_bounds__(128, 4) gemm_kernel(
    const float* __restrict__ x, const float* __restrict__ W)
{
    __shared__ float4 Ws[64][16];  // W row-major [k][c4]

    int tid = threadIdx.x;
    for (int i = tid; i < 64 * 16; i += 128)
        ((float4*)Ws)[i] = ((const float4*)W)[i];
    __syncthreads();

    int row = blockIdx.x * 128 + tid;
    if (row >= N_NODES) return;

    const float4* x4 = (const float4*)x + (size_t)row * 16;

    unsigned long long acc[32];
#pragma unroll
    for (int c = 0; c < 32; c++) acc[c] = 0ull;

#pragma unroll 4
    for (int k4 = 0; k4 < 16; k4++) {
        float4 xv = x4[k4];
        float xsv[4];
        xsv[0] = xv.x; xsv[1] = xv.y; xsv[2] = xv.z; xsv[3] = xv.w;
#pragma unroll
        for (int j = 0; j < 4; j++) {
            unsigned long long xk2;
            asm("mov.b64 %0, {%1, %1};" : "=l"(xk2) : "f"(xsv[j]));
            int k = k4 * 4 + j;
            const ulonglong2* wrow = (const ulonglong2*)&Ws[k][0];
#pragma unroll
            for (int c = 0; c < 16; c++) {
                ulonglong2 w = wrow[c];
                FMA2(acc[2 * c],     xk2, w.x);
                FMA2(acc[2 * c + 1], xk2, w.y);
            }
        }
    }

    uint4* yrow = (uint4*)(g_yh0 + (size_t)row * H);
#pragma unroll
    for (int u = 0; u < 8; u++) {
        uint4 o;
        unsigned r[4];
#pragma unroll
        for (int j = 0; j < 4; j++) {
            float lo, hi;
            asm("mov.b64 {%0, %1}, %2;" : "=f"(lo), "=f"(hi) : "l"(acc[u * 4 + j]));
            __half2 hv = __floats2half2_rn(lo, hi);
            r[j] = *(unsigned*)&hv;
        }
        o.x = r[0]; o.y = r[1]; o.z = r[2]; o.w = r[3];
        yrow[u] = o;
    }
}

// Fused pull: one warp per dst node.
//   t = sum_e y[src_e]*norm_e + y[dst]*dinv^2 + bias        (fp32)
//   mode==1: y_next[dst] = t @ Wnext  (fp16, ping-pong buffer)
//   mode==0: out[dst] = t             (fp32, final layer)
// ysel: 0 = read g_yh0/write g_yh1 ; 1 = read g_yh1/write g_yh0
__global__ void __launch_bounds__(256) pull_kernel(
    const float* __restrict__ bias, const float* __restrict__ Wnext,
    float* __restrict__ out_ext, int ysel, int mode)
{
    __shared__ unsigned long long Ws2[64][32];  // Ws2[k][c] = {W[k][2c], W[k][2c+1]}
    __shared__ float tbuf[8][64];

    const __half* yin = ysel ? g_yh1 : g_yh0;
    __half* yout = ysel ? g_yh0 : g_yh1;

    int tid = threadIdx.x;
    if (mode) {
        for (int i = tid; i < 64 * 16; i += 256)
            ((float4*)Ws2)[i] = ((const float4*)Wnext)[i];
    }
    __syncthreads();

    int warp = (blockIdx.x * 256 + tid) >> 5;   // grid covers exactly N_NODES
    int dst = warp;
    int lane = tid & 31;
    int wib = (tid >> 5) & 7;
    int q = lane & 7;
    int h = lane >> 3;

    int beg = g_rowptr[dst] + g_boff[dst >> 10];
    int end = (dst + 1 < N_NODES) ? (g_rowptr[dst + 1] + g_boff[(dst + 1) >> 10])
                                  : N_EDGES;

    const uint4* y16 = (const uint4*)yin;  // 8 uint4 per row

    float4 a0 = make_float4(0.f, 0.f, 0.f, 0.f);
    float4 a1 = make_float4(0.f, 0.f, 0.f, 0.f);

    for (int j = beg + h; j < end; j += 4) {
        int2 m = g_edge[j];
        float nm = __int_as_float(m.y);
        uint4 v = y16[(size_t)m.x * 8 + q];
        const __half2* hp = (const __half2*)&v;
        float2 f0 = __half22float2(hp[0]);
        float2 f1 = __half22float2(hp[1]);
        float2 f2 = __half22float2(hp[2]);
        float2 f3 = __half22float2(hp[3]);
        a0.x = fmaf(f0.x, nm, a0.x); a0.y = fmaf(f0.y, nm, a0.y);
        a0.z = fmaf(f1.x, nm, a0.z); a0.w = fmaf(f1.y, nm, a0.w);
        a1.x = fmaf(f2.x, nm, a1.x); a1.y = fmaf(f2.y, nm, a1.y);
        a1.z = fmaf(f3.x, nm, a1.z); a1.w = fmaf(f3.y, nm, a1.w);
    }

#pragma unroll
    for (int off = 8; off < 32; off <<= 1) {
        a0.x += __shfl_xor_sync(0xFFFFFFFFu, a0.x, off);
        a0.y += __shfl_xor_sync(0xFFFFFFFFu, a0.y, off);
        a0.z += __shfl_xor_sync(0xFFFFFFFFu, a0.z, off);
        a0.w += __shfl_xor_sync(0xFFFFFFFFu, a0.w, off);
        a1.x += __shfl_xor_sync(0xFFFFFFFFu, a1.x, off);
        a1.y += __shfl_xor_sync(0xFFFFFFFFu, a1.y, off);
        a1.z += __shfl_xor_sync(0xFFFFFFFFu, a1.z, off);
        a1.w += __shfl_xor_sync(0xFFFFFFFFu, a1.w, off);
    }

    if (h == 0) {
        float di = g_dinv[dst];
        float s2 = di * di;
        uint4 v = y16[(size_t)dst * 8 + q];
        const __half2* hp = (const __half2*)&v;
        float2 f0 = __half22float2(hp[0]);
        float2 f1 = __half22float2(hp[1]);
        float2 f2 = __half22float2(hp[2]);
        float2 f3 = __half22float2(hp[3]);
        float4 bv0 = ((const float4*)bias)[q * 2];
        float4 bv1 = ((const float4*)bias)[q * 2 + 1];
        float4 t0, t1;
        t0.x = fmaf(f0.x, s2, a0.x) + bv0.x;
        t0.y = fmaf(f0.y, s2, a0.y) + bv0.y;
        t0.z = fmaf(f1.x, s2, a0.z) + bv0.z;
        t0.w = fmaf(f1.y, s2, a0.w) + bv0.w;
        t1.x = fmaf(f2.x, s2, a1.x) + bv1.x;
        t1.y = fmaf(f2.y, s2, a1.y) + bv1.y;
        t1.z = fmaf(f3.x, s2, a1.z) + bv1.z;
        t1.w = fmaf(f3.y, s2, a1.w) + bv1.w;
        if (mode) {
            ((float4*)&tbuf[wib][0])[q * 2]     = t0;
            ((float4*)&tbuf[wib][0])[q * 2 + 1] = t1;
        } else {
            float4* orow = (float4*)out_ext + (size_t)dst * 16;
            orow[q * 2]     = t0;
            orow[q * 2 + 1] = t1;
        }
    }

    if (mode) {
        __syncwarp();
        const float* tb = &tbuf[wib][0];
        unsigned long long acc = 0ull;  // cols {2*lane, 2*lane+1}
#pragma unroll 16
        for (int k = 0; k < 64; k++) {
            float xk = tb[k];
            unsigned long long xk2;
            asm("mov.b64 %0, {%1, %1};" : "=l"(xk2) : "f"(xk));
            FMA2(acc, xk2, Ws2[k][lane]);
        }
        float lo, hi;
        asm("mov.b64 {%0, %1}, %2;" : "=f"(lo), "=f"(hi) : "l"(acc));
        __half2 hv = __floats2half2_rn(lo, hi);
        ((__half2*)yout)[(size_t)dst * 32 + lane] = hv;
    }
}

extern "C" void kernel_launch(void* const* d_in, const int* in_sizes, int n_in,
                              void* d_out, int out_size)
{
    const float* emb = (const float*)d_in[0];
    const int*   ei  = (const int*)d_in[1];
    const float* W1  = (const float*)d_in[2];
    const float* b1  = (const float*)d_in[3];
    const float* W2  = (const float*)d_in[4];
    const float* b2  = (const float*)d_in[5];
    const float* W3  = (const float*)d_in[6];
    const float* b3  = (const float*)d_in[7];
    float* out = (float*)d_out;

    const int node_blocks = (N_NODES + 255) / 256;
    const int edge_blocks = (N_EDGES + 255) / 256;
    const int gemm_blocks = (N_NODES + 127) / 128;
    const int pull_blocks = N_NODES / 8;   // 12500, exact

    // ---- CSR build (once per launch) ----
    zero_kernel<<<node_blocks, 256>>>();
    hist_kernel<<<edge_blocks, 256>>>(ei);
    scanA_kernel<<<SCAN_B, SCAN_T>>>();
    fill_kernel<<<edge_blocks, 256>>>(ei);

    // ---- Layer 1 GEMM: emb @ W1 -> y0 (fp16) ----
    gemm_kernel<<<gemm_blocks, 128>>>(emb, W1);

    // ---- Pull 1 (fused with W2): y0 -> y1 ----
    pull_kernel<<<pull_blocks, 256>>>(b1, W2, out, /*ysel=*/0, /*mode=*/1);
    // ---- Pull 2 (fused with W3): y1 -> y0 ----
    pull_kernel<<<pull_blocks, 256>>>(b2, W3, out, /*ysel=*/1, /*mode=*/1);
    // ---- Pull 3 (final): y0 -> d_out fp32 ----
    pull_kernel<<<pull_blocks, 256>>>(b3, W3, out, /*ysel=*/0, /*mode=*/0);
}

// round 7
// speedup vs baseline: 1.1813x; 1.1813x over previous
#include <cuda_runtime.h>
#include <cuda_fp16.h>
#include <math.h>

#define N_NODES 100000
#define N_EDGES 1600000
#define H 64
#define SCAN_T 1024
#define SCAN_B ((N_NODES + SCAN_T - 1) / SCAN_T)   // 98

// Scratch (device globals — no allocation allowed)
__device__ int    g_degi[N_NODES];
__device__ float  g_dinv[N_NODES];
__device__ int    g_rowptr[N_NODES];       // exclusive-within-block partials
__device__ int    g_bsum[SCAN_B];
__device__ int    g_boff[SCAN_B];          // exclusive block offsets
__device__ int    g_rank[N_EDGES];         // edge rank within its dst row
__device__ int    g_ticket;
__device__ int2   g_edge[N_EDGES];         // {src, norm-as-bits}
__device__ __half g_yh[(size_t)N_NODES * H];   // y = xW (fp16, gather target)
__device__ __half g_xh[(size_t)N_NODES * H];   // intermediate layer output (fp16)

#define FMA2(acc, a, b) \
    asm("fma.rn.f32x2 %0, %1, %2, %0;" : "+l"(acc) : "l"(a), "l"(b))

__global__ void zero_kernel() {
    int i = blockIdx.x * blockDim.x + threadIdx.x;
    if (i < N_NODES) g_degi[i] = 0;
    if (i == 0) g_ticket = 0;
}

// Histogram over dst; the returned old count is this edge's rank in its row.
__global__ void hist_kernel(const int* __restrict__ ei) {
    int e = blockIdx.x * blockDim.x + threadIdx.x;
    if (e < N_EDGES) g_rank[e] = atomicAdd(&g_degi[ei[N_EDGES + e]], 1);
}

// Per-block scan of degrees (+ fused dinv). Last block to finish also scans
// the 98 block sums into g_boff (decoupled via ticket + threadfence).
__global__ void __launch_bounds__(SCAN_T) scanA_kernel() {
    __shared__ int s[SCAN_T];
    __shared__ int s2[128];
    __shared__ int isLast;
    int t = threadIdx.x;
    int i = blockIdx.x * SCAN_T + t;
    int v = (i < N_NODES) ? g_degi[i] : 0;
    if (i < N_NODES) g_dinv[i] = rsqrtf((float)(v + 1));
    s[t] = v;
    __syncthreads();
    for (int off = 1; off < SCAN_T; off <<= 1) {
        int tmp = 0;
        if (t >= off) tmp = s[t - off];
        __syncthreads();
        if (t >= off) s[t] += tmp;
        __syncthreads();
    }
    if (i < N_NODES) g_rowptr[i] = s[t] - v;  // exclusive within block
    if (t == SCAN_T - 1) g_bsum[blockIdx.x] = s[t];

    if (t == 0) {
        __threadfence();
        int prev = atomicAdd(&g_ticket, 1);
        isLast = (prev == gridDim.x - 1) ? 1 : 0;
    }
    __syncthreads();
    if (!isLast) return;
    __threadfence();  // acquire bsum writes

    int v2 = (t < SCAN_B) ? g_bsum[t] : 0;
    if (t < 128) s2[t] = v2;
    __syncthreads();
    for (int off = 1; off < 128; off <<= 1) {
        int tmp = 0;
        if (t >= off && t < 128) tmp = s2[t - off];
        __syncthreads();
        if (t >= off && t < 128) s2[t] += tmp;
        __syncthreads();
    }
    if (t < SCAN_B) g_boff[t] = s2[t] - v2;  // exclusive
}

// CSR fill; no atomics (rank precomputed by hist), boff applied on the fly.
__global__ void fill_kernel(const int* __restrict__ ei) {
    int e = blockIdx.x * blockDim.x + threadIdx.x;
    if (e >= N_EDGES) return;
    int s = ei[e];
    int d = ei[N_EDGES + e];
    int p = g_rowptr[d] + g_boff[d >> 10] + g_rank[e];
    int2 m;
    m.x = s;
    m.y = __float_as_int(g_dinv[s] * g_dinv[d]);
    g_edge[p] = m;
}

// y = x @ W (fp16 out). xsel: 0 = fp32 embeddings, 1 = fp16 g_xh.
__global__ void __launch_bounds__(128, 4) gemm_kernel(
    const float* __restrict__ x_ext, const float* __restrict__ W, int xsel)
{
    __shared__ float4 Ws[64][16];  // W row-major [k][c4]

    int tid = threadIdx.x;
    for (int i = tid; i < 64 * 16; i += 128)
        ((float4*)Ws)[i] = ((const float4*)W)[i];
    __syncthreads();

    int row = blockIdx.x * 128 + tid;
    if (row >= N_NODES) return;

    unsigned long long acc[32];
#pragma unroll
    for (int c = 0; c < 32; c++) acc[c] = 0ull;

    if (xsel == 0) {
        const float4* x4 = (const float4*)x_ext + (size_t)row * 16;
#pragma unroll 4
        for (int k4 = 0; k4 < 16; k4++) {
            float4 xv = x4[k4];
            float xsv[4];
            xsv[0] = xv.x; xsv[1] = xv.y; xsv[2] = xv.z; xsv[3] = xv.w;
#pragma unroll
            for (int j = 0; j < 4; j++) {
                unsigned long long xk2;
                asm("mov.b64 %0, {%1, %1};" : "=l"(xk2) : "f"(xsv[j]));
                int k = k4 * 4 + j;
                const ulonglong2* wrow = (const ulonglong2*)&Ws[k][0];
#pragma unroll
                for (int c = 0; c < 16; c++) {
                    ulonglong2 w = wrow[c];
                    FMA2(acc[2 * c],     xk2, w.x);
                    FMA2(acc[2 * c + 1], xk2, w.y);
                }
            }
        }
    } else {
        const uint4* xr = (const uint4*)(g_xh + (size_t)row * H);  // 8 uint4
#pragma unroll 2
        for (int u = 0; u < 8; u++) {
            uint4 v = xr[u];
            const __half2* hp = (const __half2*)&v;
            float xsv[8];
#pragma unroll
            for (int p = 0; p < 4; p++) {
                float2 f = __half22float2(hp[p]);
                xsv[2 * p] = f.x; xsv[2 * p + 1] = f.y;
            }
#pragma unroll
            for (int j = 0; j < 8; j++) {
                unsigned long long xk2;
                asm("mov.b64 %0, {%1, %1};" : "=l"(xk2) : "f"(xsv[j]));
                int k = u * 8 + j;
                const ulonglong2* wrow = (const ulonglong2*)&Ws[k][0];
#pragma unroll
                for (int c = 0; c < 16; c++) {
                    ulonglong2 w = wrow[c];
                    FMA2(acc[2 * c],     xk2, w.x);
                    FMA2(acc[2 * c + 1], xk2, w.y);
                }
            }
        }
    }

    uint4* yrow = (uint4*)(g_yh + (size_t)row * H);
#pragma unroll
    for (int u = 0; u < 8; u++) {
        uint4 o;
        unsigned r[4];
#pragma unroll
        for (int j = 0; j < 4; j++) {
            float lo, hi;
            asm("mov.b64 {%0, %1}, %2;" : "=f"(lo), "=f"(hi) : "l"(acc[u * 4 + j]));
            __half2 hv = __floats2half2_rn(lo, hi);
            r[j] = *(unsigned*)&hv;
        }
        o.x = r[0]; o.y = r[1]; o.z = r[2]; o.w = r[3];
        yrow[u] = o;
    }
}

// Pull: one warp per dst. q = lane&7 (16B = 8 fp16 cols), h = lane>>3 (4 edge slots).
// t = sum_e y[src_e]*norm_e + y[dst]*dinv^2 + b   (fp32 accumulate)
// mode==1: g_xh[dst] = t (fp16) ; mode==0: out[dst] = t (fp32, final)
__global__ void __launch_bounds__(256) pull_kernel(
    const float* __restrict__ bias, float* __restrict__ out_ext, int mode)
{
    int warp = (blockIdx.x * 256 + threadIdx.x) >> 5;   // grid exact: N_NODES warps
    int dst = warp;
    int lane = threadIdx.x & 31;
    int q = lane & 7;
    int h = lane >> 3;

    int beg = g_rowptr[dst] + g_boff[dst >> 10];
    int end = (dst + 1 < N_NODES) ? (g_rowptr[dst + 1] + g_boff[(dst + 1) >> 10])
                                  : N_EDGES;

    const uint4* y16 = (const uint4*)g_yh;  // 8 uint4 per row

    float4 a0 = make_float4(0.f, 0.f, 0.f, 0.f);
    float4 a1 = make_float4(0.f, 0.f, 0.f, 0.f);

    for (int j = beg + h; j < end; j += 4) {
        int2 m = g_edge[j];
        float nm = __int_as_float(m.y);
        uint4 v = y16[(size_t)m.x * 8 + q];
        const __half2* hp = (const __half2*)&v;
        float2 f0 = __half22float2(hp[0]);
        float2 f1 = __half22float2(hp[1]);
        float2 f2 = __half22float2(hp[2]);
        float2 f3 = __half22float2(hp[3]);
        a0.x = fmaf(f0.x, nm, a0.x); a0.y = fmaf(f0.y, nm, a0.y);
        a0.z = fmaf(f1.x, nm, a0.z); a0.w = fmaf(f1.y, nm, a0.w);
        a1.x = fmaf(f2.x, nm, a1.x); a1.y = fmaf(f2.y, nm, a1.y);
        a1.z = fmaf(f3.x, nm, a1.z); a1.w = fmaf(f3.y, nm, a1.w);
    }

#pragma unroll
    for (int off = 8; off < 32; off <<= 1) {
        a0.x += __shfl_xor_sync(0xFFFFFFFFu, a0.x, off);
        a0.y += __shfl_xor_sync(0xFFFFFFFFu, a0.y, off);
        a0.z += __shfl_xor_sync(0xFFFFFFFFu, a0.z, off);
        a0.w += __shfl_xor_sync(0xFFFFFFFFu, a0.w, off);
        a1.x += __shfl_xor_sync(0xFFFFFFFFu, a1.x, off);
        a1.y += __shfl_xor_sync(0xFFFFFFFFu, a1.y, off);
        a1.z += __shfl_xor_sync(0xFFFFFFFFu, a1.z, off);
        a1.w += __shfl_xor_sync(0xFFFFFFFFu, a1.w, off);
    }

    if (h == 0) {
        float di = g_dinv[dst];
        float s2 = di * di;
        uint4 v = y16[(size_t)dst * 8 + q];
        const __half2* hp = (const __half2*)&v;
        float2 f0 = __half22float2(hp[0]);
        float2 f1 = __half22float2(hp[1]);
        float2 f2 = __half22float2(hp[2]);
        float2 f3 = __half22float2(hp[3]);
        float4 bv0 = ((const float4*)bias)[q * 2];
        float4 bv1 = ((const float4*)bias)[q * 2 + 1];
        float4 t0, t1;
        t0.x = fmaf(f0.x, s2, a0.x) + bv0.x;
        t0.y = fmaf(f0.y, s2, a0.y) + bv0.y;
        t0.z = fmaf(f1.x, s2, a0.z) + bv0.z;
        t0.w = fmaf(f1.y, s2, a0.w) + bv0.w;
        t1.x = fmaf(f2.x, s2, a1.x) + bv1.x;
        t1.y = fmaf(f2.y, s2, a1.y) + bv1.y;
        t1.z = fmaf(f3.x, s2, a1.z) + bv1.z;
        t1.w = fmaf(f3.y, s2, a1.w) + bv1.w;
        if (mode) {
            // pack 8 floats -> 8 halves -> one uint4 write
            uint4 o;
            __half2 h0 = __floats2half2_rn(t0.x, t0.y);
            __half2 h1 = __floats2half2_rn(t0.z, t0.w);
            __half2 h2 = __floats2half2_rn(t1.x, t1.y);
            __half2 h3 = __floats2half2_rn(t1.z, t1.w);
            o.x = *(unsigned*)&h0; o.y = *(unsigned*)&h1;
            o.z = *(unsigned*)&h2; o.w = *(unsigned*)&h3;
            ((uint4*)g_xh)[(size_t)dst * 8 + q] = o;
        } else {
            float4* orow = (float4*)out_ext + (size_t)dst * 16;
            orow[q * 2]     = t0;
            orow[q * 2 + 1] = t1;
        }
    }
}

extern "C" void kernel_launch(void* const* d_in, const int* in_sizes, int n_in,
                              void* d_out, int out_size)
{
    const float* emb = (const float*)d_in[0];
    const int*   ei  = (const int*)d_in[1];
    const float* W1  = (const float*)d_in[2];
    const float* b1  = (const float*)d_in[3];
    const float* W2  = (const float*)d_in[4];
    const float* b2  = (const float*)d_in[5];
    const float* W3  = (const float*)d_in[6];
    const float* b3  = (const float*)d_in[7];
    float* out = (float*)d_out;

    const int node_blocks = (N_NODES + 255) / 256;
    const int edge_blocks = (N_EDGES + 255) / 256;
    const int gemm_blocks = (N_NODES + 127) / 128;
    const int pull_blocks = N_NODES / 8;   // 12500, exact

    // ---- CSR build (once per launch) ----
    zero_kernel<<<node_blocks, 256>>>();
    hist_kernel<<<edge_blocks, 256>>>(ei);
    scanA_kernel<<<SCAN_B, SCAN_T>>>();
    fill_kernel<<<edge_blocks, 256>>>(ei);

    // ---- Layer 1: emb -> g_xh ----
    gemm_kernel<<<gemm_blocks, 128>>>(emb, W1, /*xsel=*/0);
    pull_kernel<<<pull_blocks, 256>>>(b1, out, /*mode=*/1);

    // ---- Layer 2: g_xh -> g_xh ----
    gemm_kernel<<<gemm_blocks, 128>>>(emb, W2, /*xsel=*/1);
    pull_kernel<<<pull_blocks, 256>>>(b2, out, /*mode=*/1);

    // ---- Layer 3: g_xh -> d_out (fp32) ----
    gemm_kernel<<<gemm_blocks, 128>>>(emb, W3, /*xsel=*/1);
    pull_kernel<<<pull_blocks, 256>>>(b3, out, /*mode=*/0);
}